// round 3
// baseline (speedup 1.0000x reference)
#include <cuda_runtime.h>
#include <cstdint>
#include <cstdio>

// Problem constants (fixed by the reference)
#define NN 50000
#define EE 800000
#define F_IN 128
#define HDIM 256
#define CDIM 32

// ---------------- scratch (static device memory; no allocs allowed) -----------
__device__ float g_eh [(size_t)EE * F_IN];   // relu(w1)  -> layer-2 edge features
__device__ float g_m  [(size_t)EE * HDIM];   // message buffer (layer1 uses 128 cols)
__device__ float g_r  [(size_t)EE * HDIM];   // MLP intermediate
__device__ float g_cos[EE];
__device__ float g_inv[NN];
__device__ float g_h1 [(size_t)NN * HDIM];   // relu(layer-1 output)
__device__ float g_hN [(size_t)NN * HDIM];   // scatter accumulator (both layers)
__device__ float g_cnt[NN];                  // in-degree (float)

// ---------------- small utility kernels --------------------------------------
__global__ void k_zero(float* __restrict__ p, int n) {
    int i = blockIdx.x * blockDim.x + threadIdx.x;
    if (i < n) p[i] = 0.f;
}

__global__ void k_degree(const int* __restrict__ dst, float* __restrict__ cnt, int E) {
    int e = blockIdx.x * blockDim.x + threadIdx.x;
    if (e < E) atomicAdd(&cnt[dst[e]], 1.f);
}

// 1 / max(||row||, eps), one warp per node
__global__ void k_invn(const float* __restrict__ h, float* __restrict__ inv, int Nn, int F) {
    int gw   = (blockIdx.x * blockDim.x + threadIdx.x) >> 5;
    int lane = threadIdx.x & 31;
    if (gw >= Nn) return;
    const float* row = h + (size_t)gw * F;
    float s = 0.f;
    for (int k = lane; k < F; k += 32) { float v = row[k]; s += v * v; }
    #pragma unroll
    for (int o = 16; o; o >>= 1) s += __shfl_xor_sync(0xFFFFFFFFu, s, o);
    if (lane == 0) inv[gw] = 1.f / fmaxf(sqrtf(s), 1e-12f);
}

// hN[n,f] /= max(cnt[n],1)
__global__ void k_div(float* __restrict__ hN, const float* __restrict__ cnt, int Nn, int F) {
    int i = blockIdx.x * blockDim.x + threadIdx.x;
    if (i < Nn * F) hN[i] /= fmaxf(cnt[i / F], 1.f);
}

// Layer-1 fused edge kernel: one block (128 thr) per edge.
//   w   = ef @ We1 + be1                (K=2 "GEMM", done directly)
//   cos = dot(h[src], h[dst]) * inv[src] * inv[dst]
//   eh  = relu(w)        (layer-2 edge features)
//   m   = cos * w * h[src]
__global__ void k_edge1(const float* __restrict__ hf, const int* __restrict__ src,
                        const int* __restrict__ dst, const float* __restrict__ inv,
                        const float* __restrict__ ef, const float* __restrict__ We,
                        const float* __restrict__ be,
                        float* __restrict__ eh, float* __restrict__ m) {
    int e = blockIdx.x;
    int t = threadIdx.x;
    int s = src[e], d = dst[e];
    float a = hf[(size_t)s * F_IN + t];
    float b = hf[(size_t)d * F_IN + t];
    float p = a * b;
    #pragma unroll
    for (int o = 16; o; o >>= 1) p += __shfl_xor_sync(0xFFFFFFFFu, p, o);
    __shared__ float sm[4];
    __shared__ float scos;
    if ((t & 31) == 0) sm[t >> 5] = p;
    __syncthreads();
    if (t == 0) {
        float dsum = sm[0] + sm[1] + sm[2] + sm[3];
        scos = dsum * inv[s] * inv[d];
    }
    __syncthreads();
    float cs = scos;
    float e0 = ef[2 * e], e1 = ef[2 * e + 1];
    float w  = e0 * We[t] + e1 * We[F_IN + t] + be[t];
    eh[(size_t)e * F_IN + t] = fmaxf(w, 0.f);
    m [(size_t)e * F_IN + t] = cs * w * a;
}

// Layer-2 per-edge cosine: one block (256 thr) per edge over h1 (256-dim)
__global__ void k_cos2(const float* __restrict__ h, const int* __restrict__ src,
                       const int* __restrict__ dst, const float* __restrict__ inv,
                       float* __restrict__ cosv) {
    int e = blockIdx.x;
    int t = threadIdx.x;
    int s = src[e], d = dst[e];
    float p = h[(size_t)s * HDIM + t] * h[(size_t)d * HDIM + t];
    #pragma unroll
    for (int o = 16; o; o >>= 1) p += __shfl_xor_sync(0xFFFFFFFFu, p, o);
    __shared__ float sm[8];
    if ((t & 31) == 0) sm[t >> 5] = p;
    __syncthreads();
    if (t == 0) {
        float dsum = 0.f;
        #pragma unroll
        for (int i = 0; i < 8; i++) dsum += sm[i];
        cosv[e] = dsum * inv[s] * inv[d];
    }
}

// ---------------- generic tiled SGEMM with fused epilogues --------------------
// C[M,Nout] = epi( [A0|A1] @ W + bias )
// BM=128, BN=128, BK=8, thread tile 8x8, 256 threads.
enum { EPI_RELU = 0, EPI_MSG = 1, EPI_SCAT = 2 };

template <int EPI>
__global__ __launch_bounds__(256, 2)
void k_gemm(const float* __restrict__ A0, int K0,
            const float* __restrict__ A1, int K1,
            const float* __restrict__ W, const float* __restrict__ bias,
            float* __restrict__ C, int M, int Nout,
            const float* __restrict__ cosv, const int* __restrict__ idx,
            const float* __restrict__ htab, int hld) {
    __shared__ float As[8][132];   // +4 pad kills STS bank conflicts
    __shared__ float Bs[8][128];

    const int tid  = threadIdx.x;
    const int brow = blockIdx.y * 128;
    const int bcol = blockIdx.x * 128;
    const int K    = K0 + K1;

    const int arow = tid >> 1, acol = (tid & 1) * 4;   // A tile: 128x8, 4 floats/thr
    const int brw  = tid >> 5, bcl  = (tid & 31) * 4;  // B tile: 8x128, 4 floats/thr
    const int ty   = tid >> 4, tx   = tid & 15;

    float acc[8][8];
    #pragma unroll
    for (int i = 0; i < 8; i++)
        #pragma unroll
        for (int j = 0; j < 8; j++) acc[i][j] = 0.f;

    const int grow = brow + arow;

    for (int kt = 0; kt < K; kt += 8) {
        float4 av = make_float4(0.f, 0.f, 0.f, 0.f);
        if (grow < M) {
            const float* ap = (kt < K0)
                ? A0 + (size_t)grow * K0 + (kt + acol)
                : A1 + (size_t)grow * K1 + (kt - K0 + acol);
            av = *(const float4*)ap;
        }
        As[acol + 0][arow] = av.x;
        As[acol + 1][arow] = av.y;
        As[acol + 2][arow] = av.z;
        As[acol + 3][arow] = av.w;
        *(float4*)&Bs[brw][bcl] =
            *(const float4*)(W + (size_t)(kt + brw) * Nout + (bcol + bcl));
        __syncthreads();

        #pragma unroll
        for (int k = 0; k < 8; k++) {
            float a[8], b[8];
            *(float4*)(a)     = *(const float4*)&As[k][ty * 8];
            *(float4*)(a + 4) = *(const float4*)&As[k][ty * 8 + 4];
            *(float4*)(b)     = *(const float4*)&Bs[k][tx * 8];
            *(float4*)(b + 4) = *(const float4*)&Bs[k][tx * 8 + 4];
            #pragma unroll
            for (int i = 0; i < 8; i++)
                #pragma unroll
                for (int j = 0; j < 8; j++) acc[i][j] += a[i] * b[j];
        }
        __syncthreads();
    }

    const int c0 = bcol + tx * 8;
    float bs[8];
    #pragma unroll
    for (int j = 0; j < 8; j++) bs[j] = bias[c0 + j];

    #pragma unroll
    for (int i = 0; i < 8; i++) {
        const int r = brow + ty * 8 + i;
        if (r >= M) continue;
        if (EPI == EPI_RELU) {
            float4 v0, v1;
            v0.x = fmaxf(acc[i][0] + bs[0], 0.f);
            v0.y = fmaxf(acc[i][1] + bs[1], 0.f);
            v0.z = fmaxf(acc[i][2] + bs[2], 0.f);
            v0.w = fmaxf(acc[i][3] + bs[3], 0.f);
            v1.x = fmaxf(acc[i][4] + bs[4], 0.f);
            v1.y = fmaxf(acc[i][5] + bs[5], 0.f);
            v1.z = fmaxf(acc[i][6] + bs[6], 0.f);
            v1.w = fmaxf(acc[i][7] + bs[7], 0.f);
            float* cp = C + (size_t)r * Nout + c0;
            *(float4*)cp       = v0;
            *(float4*)(cp + 4) = v1;
        } else if (EPI == EPI_MSG) {
            // m = cos[r] * (acc+bias) * htab[idx[r], col]
            const float cs = cosv[r];
            const float* hrow = htab + (size_t)idx[r] * hld + c0;
            float4 h0 = *(const float4*)hrow;
            float4 h1 = *(const float4*)(hrow + 4);
            float4 v0, v1;
            v0.x = (acc[i][0] + bs[0]) * cs * h0.x;
            v0.y = (acc[i][1] + bs[1]) * cs * h0.y;
            v0.z = (acc[i][2] + bs[2]) * cs * h0.z;
            v0.w = (acc[i][3] + bs[3]) * cs * h0.w;
            v1.x = (acc[i][4] + bs[4]) * cs * h1.x;
            v1.y = (acc[i][5] + bs[5]) * cs * h1.y;
            v1.z = (acc[i][6] + bs[6]) * cs * h1.z;
            v1.w = (acc[i][7] + bs[7]) * cs * h1.w;
            float* cp = C + (size_t)r * Nout + c0;
            *(float4*)cp       = v0;
            *(float4*)(cp + 4) = v1;
        } else {  // EPI_SCAT: relu then atomic scatter-add into C[idx[r]]
            float4 v0, v1;
            v0.x = fmaxf(acc[i][0] + bs[0], 0.f);
            v0.y = fmaxf(acc[i][1] + bs[1], 0.f);
            v0.z = fmaxf(acc[i][2] + bs[2], 0.f);
            v0.w = fmaxf(acc[i][3] + bs[3], 0.f);
            v1.x = fmaxf(acc[i][4] + bs[4], 0.f);
            v1.y = fmaxf(acc[i][5] + bs[5], 0.f);
            v1.z = fmaxf(acc[i][6] + bs[6], 0.f);
            v1.w = fmaxf(acc[i][7] + bs[7], 0.f);
            float* cp = C + (size_t)idx[r] * Nout + c0;
            atomicAdd((float4*)cp, v0);          // sm_90+ vector red
            atomicAdd((float4*)(cp + 4), v1);
        }
    }
}

// Final: out[N,32] = [h1 | hN] @ Wl2[512,32] + bl2.  16 rows per block.
__global__ __launch_bounds__(256)
void k_final(const float* __restrict__ h1, const float* __restrict__ hN,
             const float* __restrict__ W, const float* __restrict__ bias,
             float* __restrict__ out) {
    __shared__ float sA[16][512];
    const int n0  = blockIdx.x * 16;
    const int tid = threadIdx.x;
    // load 16 concat rows (2048 float4s) cooperatively
    for (int i = tid; i < 16 * 128; i += 256) {
        int r  = i >> 7;
        int c4 = i & 127;
        const float* sp = (c4 < 64)
            ? (h1 + (size_t)(n0 + r) * HDIM + c4 * 4)
            : (hN + (size_t)(n0 + r) * HDIM + (c4 - 64) * 4);
        *(float4*)&sA[r][c4 * 4] = *(const float4*)sp;
    }
    __syncthreads();
    const int col = tid & 31;
    const int y   = tid >> 5;  // 0..7 -> rows y and y+8
    float acc0 = bias[col], acc1 = bias[col];
    #pragma unroll 8
    for (int k = 0; k < 512; k++) {
        float w = W[k * 32 + col];
        acc0 += sA[y][k] * w;
        acc1 += sA[y + 8][k] * w;
    }
    out[(size_t)(n0 + y) * 32 + col]     = acc0;
    out[(size_t)(n0 + y + 8) * 32 + col] = acc1;
}

// ---------------- launch ------------------------------------------------------
extern "C" void kernel_launch(void* const* d_in, const int* in_sizes, int n_in,
                              void* d_out, int out_size) {
    const float* node_feat = (const float*)d_in[0];
    const float* edge_feat = (const float*)d_in[1];
    const int*   src       = (const int*)d_in[2];
    const int*   dst       = (const int*)d_in[3];
    const float* We1  = (const float*)d_in[4],  *be1  = (const float*)d_in[5];
    const float* Wr1a = (const float*)d_in[6],  *br1a = (const float*)d_in[7];
    const float* Wr1b = (const float*)d_in[8],  *br1b = (const float*)d_in[9];
    const float* Wl1  = (const float*)d_in[10], *bl1  = (const float*)d_in[11];
    const float* We2  = (const float*)d_in[12], *be2  = (const float*)d_in[13];
    const float* Wr2a = (const float*)d_in[14], *br2a = (const float*)d_in[15];
    const float* Wr2b = (const float*)d_in[16], *br2b = (const float*)d_in[17];
    const float* Wl2  = (const float*)d_in[18], *bl2  = (const float*)d_in[19];
    float* out = (float*)d_out;

    float *eh, *mbuf, *rbuf, *cosv, *invv, *h1, *hN, *cnt;
    cudaGetSymbolAddress((void**)&eh,   g_eh);
    cudaGetSymbolAddress((void**)&mbuf, g_m);
    cudaGetSymbolAddress((void**)&rbuf, g_r);
    cudaGetSymbolAddress((void**)&cosv, g_cos);
    cudaGetSymbolAddress((void**)&invv, g_inv);
    cudaGetSymbolAddress((void**)&h1,   g_h1);
    cudaGetSymbolAddress((void**)&hN,   g_hN);
    cudaGetSymbolAddress((void**)&cnt,  g_cnt);

    const int ZT = 256;
    // init: zero accumulators + counts, compute degree once (shared by both layers)
    k_zero<<<(NN * HDIM + ZT - 1) / ZT, ZT>>>(hN, NN * HDIM);
    k_zero<<<(NN + ZT - 1) / ZT, ZT>>>(cnt, NN);
    k_degree<<<(EE + ZT - 1) / ZT, ZT>>>(dst, cnt, EE);

    // ---------------- layer 1 ----------------
    k_invn<<<(NN * 32 + ZT - 1) / ZT, ZT>>>(node_feat, invv, NN, F_IN);
    k_edge1<<<EE, 128>>>(node_feat, src, dst, invv, edge_feat, We1, be1, eh, mbuf);

    // r = relu(m @ Wr1a + b)
    k_gemm<EPI_RELU><<<dim3(1, EE / 128), 256>>>(
        mbuf, F_IN, nullptr, 0, Wr1a, br1a, rbuf, EE, F_IN,
        nullptr, nullptr, nullptr, 0);
    // relu(r @ Wr1b + b) scattered into hN[dst] (128-wide)
    k_gemm<EPI_SCAT><<<dim3(1, EE / 128), 256>>>(
        rbuf, F_IN, nullptr, 0, Wr1b, br1b, hN, EE, F_IN,
        nullptr, dst, nullptr, 0);
    k_div<<<(NN * F_IN + ZT - 1) / ZT, ZT>>>(hN, cnt, NN, F_IN);
    // h1 = relu([node_feat | hN] @ Wl1 + bl1)
    k_gemm<EPI_RELU><<<dim3(2, (NN + 127) / 128), 256>>>(
        node_feat, F_IN, hN, F_IN, Wl1, bl1, h1, NN, HDIM,
        nullptr, nullptr, nullptr, 0);

    // ---------------- layer 2 ----------------
    k_zero<<<(NN * HDIM + ZT - 1) / ZT, ZT>>>(hN, NN * HDIM);
    k_invn<<<(NN * 32 + ZT - 1) / ZT, ZT>>>(h1, invv, NN, HDIM);
    k_cos2<<<EE, 256>>>(h1, src, dst, invv, cosv);

    // m2 = cos * (eh @ We2 + be2) * h1[src]   (edge-weight GEMM + message fused)
    k_gemm<EPI_MSG><<<dim3(2, EE / 128), 256>>>(
        eh, F_IN, nullptr, 0, We2, be2, mbuf, EE, HDIM,
        cosv, src, h1, HDIM);
    // r = relu(m2 @ Wr2a + b)
    k_gemm<EPI_RELU><<<dim3(2, EE / 128), 256>>>(
        mbuf, HDIM, nullptr, 0, Wr2a, br2a, rbuf, EE, HDIM,
        nullptr, nullptr, nullptr, 0);
    // relu(r @ Wr2b + b) scattered into hN[dst] (256-wide)
    k_gemm<EPI_SCAT><<<dim3(2, EE / 128), 256>>>(
        rbuf, HDIM, nullptr, 0, Wr2b, br2b, hN, EE, HDIM,
        nullptr, dst, nullptr, 0);
    k_div<<<(NN * HDIM + ZT - 1) / ZT, ZT>>>(hN, cnt, NN, HDIM);

    // out = [h1 | hN] @ Wl2 + bl2
    k_final<<<NN / 16, 256>>>(h1, hN, Wl2, bl2, out);
}

// round 5
// speedup vs baseline: 2.2992x; 2.2992x over previous
#include <cuda_runtime.h>
#include <cstdint>

// Problem constants
#define NN 50000
#define EE 800000
#define F_IN 128
#define HDIM 256

// ---------------- scratch (static device memory) ------------------------------
__device__ float g_eh [(size_t)EE * F_IN];
__device__ float g_m  [(size_t)EE * HDIM];
__device__ float g_r  [(size_t)EE * HDIM];
__device__ float g_cos[EE];
__device__ float g_inv[NN];
__device__ float g_h1 [(size_t)NN * HDIM];
__device__ float g_hN [(size_t)NN * HDIM];
__device__ float g_cnt[NN];
// transposed weights: Wt[n,k] (K-major rows)
__device__ float g_wr1a[F_IN * F_IN];
__device__ float g_wr1b[F_IN * F_IN];
__device__ float g_wl1 [HDIM * 2 * F_IN];
__device__ float g_we2 [HDIM * F_IN];
__device__ float g_wr2a[HDIM * HDIM];
__device__ float g_wr2b[HDIM * HDIM];

// ---------------- helpers ------------------------------------------------------
__device__ __forceinline__ uint32_t f2tf32(float f) {
    uint32_t r; asm("cvt.rna.tf32.f32 %0, %1;" : "=r"(r) : "f"(f)); return r;
}
__device__ __forceinline__ void mma_tf32(float& d0, float& d1, float& d2, float& d3,
                                         uint32_t a0, uint32_t a1, uint32_t a2, uint32_t a3,
                                         uint32_t b0, uint32_t b1) {
    asm volatile(
        "mma.sync.aligned.m16n8k8.row.col.f32.tf32.tf32.f32 "
        "{%0,%1,%2,%3}, {%4,%5,%6,%7}, {%8,%9}, {%0,%1,%2,%3};\n"
        : "+f"(d0), "+f"(d1), "+f"(d2), "+f"(d3)
        : "r"(a0), "r"(a1), "r"(a2), "r"(a3), "r"(b0), "r"(b1));
}

// ---------------- small utility kernels ---------------------------------------
__global__ void k_zero(float* __restrict__ p, int n) {
    int i = blockIdx.x * blockDim.x + threadIdx.x;
    if (i < n) p[i] = 0.f;
}
__global__ void k_degree(const int* __restrict__ dst, float* __restrict__ cnt, int E) {
    int e = blockIdx.x * blockDim.x + threadIdx.x;
    if (e < E) atomicAdd(&cnt[dst[e]], 1.f);
}
__global__ void k_invn(const float* __restrict__ h, float* __restrict__ inv, int Nn, int F) {
    int gw   = (blockIdx.x * blockDim.x + threadIdx.x) >> 5;
    int lane = threadIdx.x & 31;
    if (gw >= Nn) return;
    const float* row = h + (size_t)gw * F;
    float s = 0.f;
    for (int k = lane; k < F; k += 32) { float v = row[k]; s += v * v; }
    #pragma unroll
    for (int o = 16; o; o >>= 1) s += __shfl_xor_sync(0xFFFFFFFFu, s, o);
    if (lane == 0) inv[gw] = 1.f / fmaxf(sqrtf(s), 1e-12f);
}
__global__ void k_div(float* __restrict__ hN, const float* __restrict__ cnt, int Nn, int F) {
    int i = blockIdx.x * blockDim.x + threadIdx.x;
    if (i < Nn * F) hN[i] /= fmaxf(cnt[i / F], 1.f);
}
// 32x32 shared transpose: Wt[n,k] = W[k,n]; K,N multiples of 32
__global__ void k_tr(const float* __restrict__ W, float* __restrict__ Wt, int K, int N) {
    __shared__ float s[32][33];
    int bx = blockIdx.x * 32, by = blockIdx.y * 32;
    int x = threadIdx.x, y = threadIdx.y;
    #pragma unroll
    for (int j = 0; j < 32; j += 8) s[y + j][x] = W[(size_t)(by + y + j) * N + bx + x];
    __syncthreads();
    #pragma unroll
    for (int j = 0; j < 32; j += 8) Wt[(size_t)(bx + y + j) * K + by + x] = s[x][y + j];
}
// Layer-1 fused edge kernel (block=128thr per edge)
__global__ void k_edge1(const float* __restrict__ hf, const int* __restrict__ src,
                        const int* __restrict__ dst, const float* __restrict__ inv,
                        const float* __restrict__ ef, const float* __restrict__ We,
                        const float* __restrict__ be,
                        float* __restrict__ eh, float* __restrict__ m) {
    int e = blockIdx.x, t = threadIdx.x;
    int s = src[e], d = dst[e];
    float a = hf[(size_t)s * F_IN + t];
    float b = hf[(size_t)d * F_IN + t];
    float p = a * b;
    #pragma unroll
    for (int o = 16; o; o >>= 1) p += __shfl_xor_sync(0xFFFFFFFFu, p, o);
    __shared__ float sm[4];
    __shared__ float scos;
    if ((t & 31) == 0) sm[t >> 5] = p;
    __syncthreads();
    if (t == 0) scos = (sm[0] + sm[1] + sm[2] + sm[3]) * inv[s] * inv[d];
    __syncthreads();
    float cs = scos;
    float e0 = ef[2 * e], e1 = ef[2 * e + 1];
    float w  = e0 * We[t] + e1 * We[F_IN + t] + be[t];
    eh[(size_t)e * F_IN + t] = fmaxf(w, 0.f);
    m [(size_t)e * F_IN + t] = cs * w * a;
}
// Layer-2 cosine: warp per edge (h is [NN,256], L2-resident)
__global__ void k_cos2(const float* __restrict__ h, const int* __restrict__ src,
                       const int* __restrict__ dst, const float* __restrict__ inv,
                       float* __restrict__ cosv) {
    int gw   = (blockIdx.x * blockDim.x + threadIdx.x) >> 5;
    int lane = threadIdx.x & 31;
    if (gw >= EE) return;
    int s = src[gw], d = dst[gw];
    const float4* ps = (const float4*)(h + (size_t)s * HDIM);
    const float4* pd = (const float4*)(h + (size_t)d * HDIM);
    float p = 0.f;
    #pragma unroll
    for (int j = 0; j < 2; j++) {
        float4 a = ps[lane + 32 * j];
        float4 b = pd[lane + 32 * j];
        p += a.x * b.x + a.y * b.y + a.z * b.z + a.w * b.w;
    }
    #pragma unroll
    for (int o = 16; o; o >>= 1) p += __shfl_xor_sync(0xFFFFFFFFu, p, o);
    if (lane == 0) cosv[gw] = p * inv[s] * inv[d];
}

// ---------------- tf32 mma.sync GEMM with fused epilogues ----------------------
// C = epi([A0|A1] @ Wt^T + bias). Wt is [BN,K] K-major. Block 128 x BN (BN = full N).
// 8 warps: wm = wid&1 (64 rows each), wn = wid>>1 (WN = BN/4 cols each).
enum { EPI_RELU = 0, EPI_MSG = 1, EPI_SCAT = 2 };

template <int BN, int EPI>
__global__ __launch_bounds__(256, 1)
void k_mgemm(const float* __restrict__ A0, int K0,
             const float* __restrict__ A1, int K1,
             const float* __restrict__ Wt, const float* __restrict__ bias,
             float* __restrict__ C, int M,
             const float* __restrict__ cosv, const int* __restrict__ idx,
             const float* __restrict__ htab) {
    constexpr int WN  = BN / 4;       // warp N tile
    constexpr int NT  = WN / 8;       // n8 tiles per warp (4 or 8)
    constexpr int NB4 = BN * 8 / 256; // B float4 loads per thread per chunk
    constexpr int SSTRIDE = 36;       // padded float stride
    constexpr int STG = (128 + BN) * SSTRIDE;

    extern __shared__ float smf[];
    __shared__ float bs[BN];

    const int tid  = threadIdx.x;
    const int wid  = tid >> 5, lane = tid & 31;
    const int wm   = wid & 1, wn = wid >> 1;
    const int lr   = lane >> 2, lc = lane & 3;
    const int brow = blockIdx.x * 128;
    const int K    = K0 + K1, NC = K >> 5;

    for (int i = tid; i < BN; i += 256) bs[i] = bias[i];

    float acc[4][NT][4];
    #pragma unroll
    for (int mt = 0; mt < 4; mt++)
        #pragma unroll
        for (int nt = 0; nt < NT; nt++)
            #pragma unroll
            for (int q = 0; q < 4; q++) acc[mt][nt][q] = 0.f;

    float4 pa[4], pb[NB4];
    // prefetch chunk 0
    {
        const int kt = 0;
        const float* Ab; int lda, off;
        if (kt < K0) { Ab = A0; lda = K0; off = kt; } else { Ab = A1; lda = K1; off = kt - K0; }
        #pragma unroll
        for (int j = 0; j < 4; j++) {
            int f = tid + j * 256, row = f >> 3, c4 = f & 7;
            int gr = brow + row;
            pa[j] = (gr < M) ? *(const float4*)(Ab + (size_t)gr * lda + off + c4 * 4)
                             : make_float4(0.f, 0.f, 0.f, 0.f);
        }
        #pragma unroll
        for (int j = 0; j < NB4; j++) {
            int f = tid + j * 256, n = f >> 3, c4 = f & 7;
            pb[j] = *(const float4*)(Wt + (size_t)n * K + kt + c4 * 4);
        }
    }

    for (int c = 0; c < NC; c++) {
        float* As = smf + (c & 1) * STG;
        float* Bs = As + 128 * SSTRIDE;
        // store prefetched chunk (convert to tf32 rounding)
        #pragma unroll
        for (int j = 0; j < 4; j++) {
            int f = tid + j * 256, row = f >> 3, c4 = f & 7;
            uint4 t;
            t.x = f2tf32(pa[j].x); t.y = f2tf32(pa[j].y);
            t.z = f2tf32(pa[j].z); t.w = f2tf32(pa[j].w);
            *(uint4*)(As + row * SSTRIDE + c4 * 4) = t;
        }
        #pragma unroll
        for (int j = 0; j < NB4; j++) {
            int f = tid + j * 256, n = f >> 3, c4 = f & 7;
            uint4 t;
            t.x = f2tf32(pb[j].x); t.y = f2tf32(pb[j].y);
            t.z = f2tf32(pb[j].z); t.w = f2tf32(pb[j].w);
            *(uint4*)(Bs + n * SSTRIDE + c4 * 4) = t;
        }
        __syncthreads();
        // prefetch next chunk
        if (c + 1 < NC) {
            const int kt = (c + 1) * 32;
            const float* Ab; int lda, off;
            if (kt < K0) { Ab = A0; lda = K0; off = kt; } else { Ab = A1; lda = K1; off = kt - K0; }
            #pragma unroll
            for (int j = 0; j < 4; j++) {
                int f = tid + j * 256, row = f >> 3, c4 = f & 7;
                int gr = brow + row;
                pa[j] = (gr < M) ? *(const float4*)(Ab + (size_t)gr * lda + off + c4 * 4)
                                 : make_float4(0.f, 0.f, 0.f, 0.f);
            }
            #pragma unroll
            for (int j = 0; j < NB4; j++) {
                int f = tid + j * 256, n = f >> 3, c4 = f & 7;
                pb[j] = *(const float4*)(Wt + (size_t)n * K + kt + c4 * 4);
            }
        }
        // compute on current chunk
        #pragma unroll
        for (int kk = 0; kk < 4; kk++) {
            const int kb = kk * 8;
            uint32_t af[4][4];
            #pragma unroll
            for (int mt = 0; mt < 4; mt++) {
                const int r = wm * 64 + mt * 16 + lr;
                af[mt][0] = __float_as_uint(As[(r + 0) * SSTRIDE + kb + lc]);
                af[mt][1] = __float_as_uint(As[(r + 8) * SSTRIDE + kb + lc]);
                af[mt][2] = __float_as_uint(As[(r + 0) * SSTRIDE + kb + lc + 4]);
                af[mt][3] = __float_as_uint(As[(r + 8) * SSTRIDE + kb + lc + 4]);
            }
            uint32_t bf[NT][2];
            #pragma unroll
            for (int nt = 0; nt < NT; nt++) {
                const int n = wn * WN + nt * 8 + lr;
                bf[nt][0] = __float_as_uint(Bs[n * SSTRIDE + kb + lc]);
                bf[nt][1] = __float_as_uint(Bs[n * SSTRIDE + kb + lc + 4]);
            }
            #pragma unroll
            for (int mt = 0; mt < 4; mt++)
                #pragma unroll
                for (int nt = 0; nt < NT; nt++)
                    mma_tf32(acc[mt][nt][0], acc[mt][nt][1], acc[mt][nt][2], acc[mt][nt][3],
                             af[mt][0], af[mt][1], af[mt][2], af[mt][3],
                             bf[nt][0], bf[nt][1]);
        }
        __syncthreads();
    }

    // ---------------- epilogue ----------------
    #pragma unroll
    for (int mt = 0; mt < 4; mt++) {
        #pragma unroll
        for (int half = 0; half < 2; half++) {
            const int r = brow + wm * 64 + mt * 16 + lr + half * 8;
            if (r >= M) continue;
            float cs = 0.f;
            const float* hrow = nullptr;
            float* cbase;
            if (EPI == EPI_MSG) {
                cs = cosv[r];
                hrow = htab + (size_t)idx[r] * BN;
                cbase = C + (size_t)r * BN;
            } else if (EPI == EPI_SCAT) {
                cbase = C + (size_t)idx[r] * BN;
            } else {
                cbase = C + (size_t)r * BN;
            }
            #pragma unroll
            for (int nt = 0; nt < NT; nt++) {
                const int col = wn * WN + nt * 8 + lc * 2;
                float v0 = acc[mt][nt][half * 2 + 0] + bs[col];
                float v1 = acc[mt][nt][half * 2 + 1] + bs[col + 1];
                if (EPI == EPI_MSG) {
                    v0 = v0 * cs * hrow[col];
                    v1 = v1 * cs * hrow[col + 1];
                } else {
                    v0 = fmaxf(v0, 0.f);
                    v1 = fmaxf(v1, 0.f);
                }
                if (EPI == EPI_SCAT)
                    atomicAdd((float2*)(cbase + col), make_float2(v0, v1));
                else
                    *(float2*)(cbase + col) = make_float2(v0, v1);
            }
        }
    }
}

// Final: out[N,32] = [h1 | hN] @ Wl2[512,32] + bl2
__global__ __launch_bounds__(256)
void k_final(const float* __restrict__ h1, const float* __restrict__ hN,
             const float* __restrict__ W, const float* __restrict__ bias,
             float* __restrict__ out) {
    __shared__ float sA[16][512];
    const int n0 = blockIdx.x * 16, tid = threadIdx.x;
    for (int i = tid; i < 16 * 128; i += 256) {
        int r = i >> 7, c4 = i & 127;
        const float* sp = (c4 < 64)
            ? (h1 + (size_t)(n0 + r) * HDIM + c4 * 4)
            : (hN + (size_t)(n0 + r) * HDIM + (c4 - 64) * 4);
        *(float4*)&sA[r][c4 * 4] = *(const float4*)sp;
    }
    __syncthreads();
    const int col = tid & 31, y = tid >> 5;
    float acc0 = bias[col], acc1 = bias[col];
    #pragma unroll 8
    for (int k = 0; k < 512; k++) {
        float w = W[k * 32 + col];
        acc0 += sA[y][k] * w;
        acc1 += sA[y + 8][k] * w;
    }
    out[(size_t)(n0 + y) * 32 + col]     = acc0;
    out[(size_t)(n0 + y + 8) * 32 + col] = acc1;
}

// ---------------- launch ------------------------------------------------------
extern "C" void kernel_launch(void* const* d_in, const int* in_sizes, int n_in,
                              void* d_out, int out_size) {
    const float* node_feat = (const float*)d_in[0];
    const float* edge_feat = (const float*)d_in[1];
    const int*   src       = (const int*)d_in[2];
    const int*   dst       = (const int*)d_in[3];
    const float* We1  = (const float*)d_in[4],  *be1  = (const float*)d_in[5];
    const float* Wr1a = (const float*)d_in[6],  *br1a = (const float*)d_in[7];
    const float* Wr1b = (const float*)d_in[8],  *br1b = (const float*)d_in[9];
    const float* Wl1  = (const float*)d_in[10], *bl1  = (const float*)d_in[11];
    const float* We2  = (const float*)d_in[12], *be2  = (const float*)d_in[13];
    const float* Wr2a = (const float*)d_in[14], *br2a = (const float*)d_in[15];
    const float* Wr2b = (const float*)d_in[16], *br2b = (const float*)d_in[17];
    const float* Wl2  = (const float*)d_in[18], *bl2  = (const float*)d_in[19];
    float* out = (float*)d_out;

    float *eh, *mbuf, *rbuf, *cosv, *invv, *h1, *hN, *cnt;
    float *wr1a, *wr1b, *wl1, *we2, *wr2a, *wr2b;
    cudaGetSymbolAddress((void**)&eh,   g_eh);
    cudaGetSymbolAddress((void**)&mbuf, g_m);
    cudaGetSymbolAddress((void**)&rbuf, g_r);
    cudaGetSymbolAddress((void**)&cosv, g_cos);
    cudaGetSymbolAddress((void**)&invv, g_inv);
    cudaGetSymbolAddress((void**)&h1,   g_h1);
    cudaGetSymbolAddress((void**)&hN,   g_hN);
    cudaGetSymbolAddress((void**)&cnt,  g_cnt);
    cudaGetSymbolAddress((void**)&wr1a, g_wr1a);
    cudaGetSymbolAddress((void**)&wr1b, g_wr1b);
    cudaGetSymbolAddress((void**)&wl1,  g_wl1);
    cudaGetSymbolAddress((void**)&we2,  g_we2);
    cudaGetSymbolAddress((void**)&wr2a, g_wr2a);
    cudaGetSymbolAddress((void**)&wr2b, g_wr2b);

    const int SM128 = 2 * (128 + 128) * 36 * 4;  // 73728
    const int SM256 = 2 * (128 + 256) * 36 * 4;  // 110592
    cudaFuncSetAttribute(k_mgemm<128, EPI_RELU>, cudaFuncAttributeMaxDynamicSharedMemorySize, SM128);
    cudaFuncSetAttribute(k_mgemm<128, EPI_SCAT>, cudaFuncAttributeMaxDynamicSharedMemorySize, SM128);
    cudaFuncSetAttribute(k_mgemm<256, EPI_RELU>, cudaFuncAttributeMaxDynamicSharedMemorySize, SM256);
    cudaFuncSetAttribute(k_mgemm<256, EPI_MSG>,  cudaFuncAttributeMaxDynamicSharedMemorySize, SM256);
    cudaFuncSetAttribute(k_mgemm<256, EPI_SCAT>, cudaFuncAttributeMaxDynamicSharedMemorySize, SM256);

    const int ZT = 256;
    dim3 trb(32, 8);
    // weight transposes (once per launch; tiny)
    k_tr<<<dim3(F_IN / 32, F_IN / 32), trb>>>(Wr1a, wr1a, F_IN, F_IN);
    k_tr<<<dim3(F_IN / 32, F_IN / 32), trb>>>(Wr1b, wr1b, F_IN, F_IN);
    k_tr<<<dim3(HDIM / 32, (2 * F_IN) / 32), trb>>>(Wl1, wl1, 2 * F_IN, HDIM);
    k_tr<<<dim3(HDIM / 32, F_IN / 32), trb>>>(We2, we2, F_IN, HDIM);
    k_tr<<<dim3(HDIM / 32, HDIM / 32), trb>>>(Wr2a, wr2a, HDIM, HDIM);
    k_tr<<<dim3(HDIM / 32, HDIM / 32), trb>>>(Wr2b, wr2b, HDIM, HDIM);

    // init accumulators + degree (shared by both layers)
    k_zero<<<(NN * F_IN + ZT - 1) / ZT, ZT>>>(hN, NN * F_IN);
    k_zero<<<(NN + ZT - 1) / ZT, ZT>>>(cnt, NN);
    k_degree<<<(EE + ZT - 1) / ZT, ZT>>>(dst, cnt, EE);

    // ---------------- layer 1 ----------------
    k_invn<<<(NN * 32 + ZT - 1) / ZT, ZT>>>(node_feat, invv, NN, F_IN);
    k_edge1<<<EE, 128>>>(node_feat, src, dst, invv, edge_feat, We1, be1, eh, mbuf);

    k_mgemm<128, EPI_RELU><<<EE / 128, 256, SM128>>>(
        mbuf, F_IN, nullptr, 0, wr1a, br1a, rbuf, EE, nullptr, nullptr, nullptr);
    k_mgemm<128, EPI_SCAT><<<EE / 128, 256, SM128>>>(
        rbuf, F_IN, nullptr, 0, wr1b, br1b, hN, EE, nullptr, dst, nullptr);
    k_div<<<(NN * F_IN + ZT - 1) / ZT, ZT>>>(hN, cnt, NN, F_IN);
    k_mgemm<256, EPI_RELU><<<(NN + 127) / 128, 256, SM256>>>(
        node_feat, F_IN, hN, F_IN, wl1, bl1, h1, NN, nullptr, nullptr, nullptr);

    // ---------------- layer 2 ----------------
    k_zero<<<(NN * HDIM + ZT - 1) / ZT, ZT>>>(hN, NN * HDIM);
    k_invn<<<(NN * 32 + ZT - 1) / ZT, ZT>>>(h1, invv, NN, HDIM);
    k_cos2<<<(EE * 32 + ZT - 1) / ZT, ZT>>>(h1, src, dst, invv, cosv);

    k_mgemm<256, EPI_MSG><<<EE / 128, 256, SM256>>>(
        eh, F_IN, nullptr, 0, we2, be2, mbuf, EE, cosv, src, h1);
    k_mgemm<256, EPI_RELU><<<EE / 128, 256, SM256>>>(
        mbuf, HDIM, nullptr, 0, wr2a, br2a, rbuf, EE, nullptr, nullptr, nullptr);
    k_mgemm<256, EPI_SCAT><<<EE / 128, 256, SM256>>>(
        rbuf, HDIM, nullptr, 0, wr2b, br2b, hN, EE, nullptr, dst, nullptr);
    k_div<<<(NN * HDIM + ZT - 1) / ZT, ZT>>>(hN, cnt, NN, HDIM);

    k_final<<<NN / 16, 256>>>(h1, hN, Wl2, bl2, out);
}